// round 14
// baseline (speedup 1.0000x reference)
#include <cuda_runtime.h>
#include <cuda_bf16.h>
#include <math.h>
#include <stdint.h>

// ---------------------------------------------------------------------------
// LeanSelfAttention, all-bf16 tensor path (fp32 accumulate everywhere):
//   LN(bf16 out) -> QKV (bf16 m16n8k16; Q bf16 pre-scaled, K/V bf16)
//   -> flash attn (bf16 QK^T and P*V, fixed-max exp2 softmax; bf16 out)
//   -> out-proj (bf16 m16n8k16, fp32 bias+residual epilogue)
// R14: GEMM rebalanced to 64x64 warp tiles / 128x256 CTA (MMA-bound, not
// smem-co-bound). Attention/LN unchanged from R13 champion.
// ---------------------------------------------------------------------------

static constexpr int HID   = 1024;
static constexpr int SEQ   = 2048;
static constexpr int BATCH = 2;
static constexpr int ROWS  = BATCH * SEQ;   // 4096
static constexpr int HEADS = 16;
static constexpr float LOG2E = 1.4426950408889634f;

// Scratch (device globals: allocation-free contract)
__device__ __nv_bfloat16 g_xln [ROWS * HID];        // LN output bf16
__device__ __nv_bfloat16 g_qbf[ROWS * HID];         // Q third bf16, PRE-SCALED log2e/8
__device__ __nv_bfloat16 g_kbf[ROWS * HID];         // K third bf16
__device__ __nv_bfloat16 g_vbf[ROWS * HID];         // V third bf16
__device__ __nv_bfloat16 g_attn[ROWS * HID];        // attention output bf16
__device__ __nv_bfloat16 g_wqkvT[3 * HID * HID];    // [N=3072][K=1024] bf16
__device__ __nv_bfloat16 g_woutT[HID * HID];        // [N=1024][K=1024] bf16

// ======================= helpers ======================
__device__ __forceinline__ uint32_t smem_u32(const void* p) {
    uint32_t a;
    asm("{ .reg .u64 t; cvta.to.shared.u64 t, %1; cvt.u32.u64 %0, t; }"
        : "=r"(a) : "l"(p));
    return a;
}
#define CP_ASYNC16(dst, src) \
    asm volatile("cp.async.cg.shared.global [%0], [%1], 16;" :: "r"(dst), "l"(src))
#define CP_COMMIT() asm volatile("cp.async.commit_group;" ::: "memory")
#define CP_WAIT(n)  asm volatile("cp.async.wait_group %0;" :: "n"(n) : "memory")

#define LDMX4(r0, r1, r2, r3, addr) \
    asm volatile("ldmatrix.sync.aligned.m8n8.x4.shared.b16 {%0,%1,%2,%3}, [%4];" \
        : "=r"(r0), "=r"(r1), "=r"(r2), "=r"(r3) : "r"(addr))

#define LDMX4T(r0, r1, r2, r3, addr) \
    asm volatile("ldmatrix.sync.aligned.m8n8.x4.trans.shared.b16 {%0,%1,%2,%3}, [%4];" \
        : "=r"(r0), "=r"(r1), "=r"(r2), "=r"(r3) : "r"(addr))

// pack two f32 -> bf16x2 (hi = first operand, lo = second)
#define CVT_BF16X2(r, hi, lo) \
    asm("cvt.rn.bf16x2.f32 %0, %1, %2;" : "=r"(r) : "f"(hi), "f"(lo))

// m16n8k16 bf16 MMA. D += A*B.
__device__ __forceinline__ void mma_bf16(float* d, const uint32_t* a, const uint32_t* b) {
    asm volatile(
        "mma.sync.aligned.m16n8k16.row.col.f32.bf16.bf16.f32 "
        "{%0,%1,%2,%3}, {%4,%5,%6,%7}, {%8,%9}, {%0,%1,%2,%3};"
        : "+f"(d[0]), "+f"(d[1]), "+f"(d[2]), "+f"(d[3])
        : "r"(a[0]), "r"(a[1]), "r"(a[2]), "r"(a[3]), "r"(b[0]), "r"(b[1]));
}

// ---------------------------------------------------------------------------
// LayerNorm, bf16 output (unchanged)
// ---------------------------------------------------------------------------
__global__ void __launch_bounds__(256) ln_kernel(const float* __restrict__ x,
                                                 const float* __restrict__ g,
                                                 const float* __restrict__ b,
                                                 __nv_bfloat16* __restrict__ y) {
    __shared__ float red[8];
    const int row = blockIdx.x;
    const int t   = threadIdx.x;

    float4 v = ((const float4*)(x + (size_t)row * HID))[t];

    float s = v.x + v.y + v.z + v.w;
    #pragma unroll
    for (int off = 16; off; off >>= 1) s += __shfl_down_sync(0xffffffffu, s, off);
    if ((t & 31) == 0) red[t >> 5] = s;
    __syncthreads();
    if (t < 32) {
        float r = (t < 8) ? red[t] : 0.f;
        #pragma unroll
        for (int off = 4; off; off >>= 1) r += __shfl_down_sync(0xffffffffu, r, off);
        if (t == 0) red[0] = r;
    }
    __syncthreads();
    const float mu = red[0] * (1.f / HID);
    __syncthreads();

    const float dx = v.x - mu, dy = v.y - mu, dz = v.z - mu, dw = v.w - mu;
    float sq = dx * dx + dy * dy + dz * dz + dw * dw;
    #pragma unroll
    for (int off = 16; off; off >>= 1) sq += __shfl_down_sync(0xffffffffu, sq, off);
    if ((t & 31) == 0) red[t >> 5] = sq;
    __syncthreads();
    if (t < 32) {
        float r = (t < 8) ? red[t] : 0.f;
        #pragma unroll
        for (int off = 4; off; off >>= 1) r += __shfl_down_sync(0xffffffffu, r, off);
        if (t == 0) red[0] = r;
    }
    __syncthreads();
    const float inv = rsqrtf(red[0] * (1.f / HID) + 1e-12f);

    const float4 gg = ((const float4*)g)[t];
    const float4 bb = ((const float4*)b)[t];
    __nv_bfloat162 o0, o1;
    o0.x = __float2bfloat16_rn(dx * inv * gg.x + bb.x);
    o0.y = __float2bfloat16_rn(dy * inv * gg.y + bb.y);
    o1.x = __float2bfloat16_rn(dz * inv * gg.z + bb.z);
    o1.y = __float2bfloat16_rn(dw * inv * gg.w + bb.w);
    __nv_bfloat16* yp = y + (size_t)row * HID + t * 4;
    *(__nv_bfloat162*)(yp)     = o0;
    *(__nv_bfloat162*)(yp + 2) = o1;
}

// ---------------------------------------------------------------------------
// Transpose + bf16 convert: in fp32 [R][C] -> out bf16 [C][R]
// ---------------------------------------------------------------------------
__global__ void __launch_bounds__(256) transpose_bf(const float* __restrict__ in,
                                                    __nv_bfloat16* __restrict__ out,
                                                    int R, int C) {
    __shared__ float tile[32][33];
    const int x  = blockIdx.x * 32 + threadIdx.x;
    const int y0 = blockIdx.y * 32;
    #pragma unroll
    for (int j = threadIdx.y; j < 32; j += 8)
        tile[j][threadIdx.x] = in[(size_t)(y0 + j) * C + x];
    __syncthreads();
    const int x2 = y0 + threadIdx.x;
    const int y2 = blockIdx.x * 32;
    #pragma unroll
    for (int j = threadIdx.y; j < 32; j += 8)
        out[(size_t)(y2 + j) * R + x2] = __float2bfloat16_rn(tile[threadIdx.x][j]);
}

// ---------------------------------------------------------------------------
// bf16 m16n8k16 GEMM, 128x256 CTA / 64x64 warp tile, 2-stage cp.async.
// K chunks of 64 bf16 (144B row stride). QKV mode routes Q/K/V thirds to
// bf16 buffers (Q pre-scaled by log2e/8).
// ---------------------------------------------------------------------------
static constexpr int GSTB   = 144;                  // smem row stride (bytes)
static constexpr int ATILE  = 128 * GSTB;           // 18432 B
static constexpr int BTILE  = 256 * GSTB;           // 36864 B
static constexpr int GSTAGE = ATILE + BTILE;        // 55296 B
static constexpr int GSMEM  = 2 * GSTAGE;           // 110592 B

__global__ void __launch_bounds__(256, 1) gemm_bf16(
        const __nv_bfloat16* __restrict__ A,
        const __nv_bfloat16* __restrict__ Bt,
        const float* __restrict__ bias,
        const float* __restrict__ resid,
        float* __restrict__ C,
        __nv_bfloat16* __restrict__ qbf,
        __nv_bfloat16* __restrict__ kbf,
        __nv_bfloat16* __restrict__ vbf,
        int M, int N, int K) {
    extern __shared__ char smem[];
    const uint32_t sb = smem_u32(smem);

    const int tid  = threadIdx.x;
    const int wid  = tid >> 5;
    const int lane = tid & 31;
    const int gid  = lane >> 2;
    const int t4   = lane & 3;
    const int wm   = wid & 1;            // 2 warp rows
    const int wn   = wid >> 1;           // 4 warp cols (64 wide each)
    const int lg   = lane >> 3;
    const int lr   = lane & 7;

    const int m0 = blockIdx.y * 128;
    const int n0 = blockIdx.x * 256;

    const int arow = (lg & 1) * 8 + lr;
    const int akof = (lg >> 1) * 16;
    const int brow = (lg >> 1) * 8 + lr;
    const int bkof = (lg & 1) * 16;

    float acc[4][8][4];
    #pragma unroll
    for (int i = 0; i < 4; i++)
        #pragma unroll
        for (int j = 0; j < 8; j++)
            #pragma unroll
            for (int q = 0; q < 4; q++) acc[i][j][q] = 0.f;

    const int NCH = K >> 6;              // 64-K chunks

    auto load_chunk = [&](int c, int buf) {
        const int kof = c * 64;
        const uint32_t abase = sb + buf * GSTAGE;
        const uint32_t bbase = abase + ATILE;
        #pragma unroll
        for (int it = 0; it < 4; it++) {             // A: 128 rows
            const int idx = tid + it * 256;
            const int row = idx >> 3;
            const int c8  = (idx & 7) * 8;
            CP_ASYNC16(abase + (uint32_t)(row * GSTB + c8 * 2),
                       A + (size_t)(m0 + row) * K + kof + c8);
        }
        #pragma unroll
        for (int it = 0; it < 8; it++) {             // B: 256 rows
            const int idx = tid + it * 256;
            const int row = idx >> 3;
            const int c8  = (idx & 7) * 8;
            CP_ASYNC16(bbase + (uint32_t)(row * GSTB + c8 * 2),
                       Bt + (size_t)(n0 + row) * K + kof + c8);
        }
        CP_COMMIT();
    };

    load_chunk(0, 0);

    for (int c = 0; c < NCH; c++) {
        const int buf = c & 1;
        if (c + 1 < NCH) { load_chunk(c + 1, buf ^ 1); CP_WAIT(1); }
        else             { CP_WAIT(0); }
        __syncthreads();

        const uint32_t abase = sb + buf * GSTAGE;
        const uint32_t bbase = abase + ATILE;

        #pragma unroll
        for (int ks = 0; ks < 4; ks++) {
            uint32_t af[4][4], bf[8][2];
            #pragma unroll
            for (int i = 0; i < 4; i++) {
                const uint32_t addr = abase +
                    (uint32_t)((wm * 64 + i * 16 + arow) * GSTB + akof + ks * 32);
                LDMX4(af[i][0], af[i][1], af[i][2], af[i][3], addr);
            }
            #pragma unroll
            for (int jp = 0; jp < 4; jp++) {
                const uint32_t addr = bbase +
                    (uint32_t)((wn * 64 + jp * 16 + brow) * GSTB + bkof + ks * 32);
                LDMX4(bf[2 * jp][0], bf[2 * jp][1], bf[2 * jp + 1][0], bf[2 * jp + 1][1], addr);
            }
            #pragma unroll
            for (int i = 0; i < 4; i++)
                #pragma unroll
                for (int j = 0; j < 8; j++)
                    mma_bf16(acc[i][j], af[i], bf[j]);
        }
        __syncthreads();
    }

    const bool q_out = (qbf != nullptr) && (n0 < HID);
    const bool k_out = (kbf != nullptr) && (n0 >= HID) && (n0 < 2 * HID);
    const bool v_out = (vbf != nullptr) && (n0 >= 2 * HID);
    const float qscale = 0.125f * LOG2E;

    #pragma unroll
    for (int i = 0; i < 4; i++) {
        const int r0 = m0 + wm * 64 + i * 16 + gid;
        #pragma unroll
        for (int j = 0; j < 8; j++) {
            const int col = n0 + wn * 64 + j * 8 + t4 * 2;
            const float2 bb = *(const float2*)(bias + col);
            float2 o0, o1;
            o0.x = acc[i][j][0] + bb.x;  o0.y = acc[i][j][1] + bb.y;
            o1.x = acc[i][j][2] + bb.x;  o1.y = acc[i][j][3] + bb.y;
            if (q_out || k_out || v_out) {
                __nv_bfloat16* dst = q_out ? qbf : (k_out ? kbf : vbf);
                const int d0 = col - (q_out ? 0 : (k_out ? HID : 2 * HID));
                if (q_out) {
                    o0.x *= qscale; o0.y *= qscale;
                    o1.x *= qscale; o1.y *= qscale;
                }
                __nv_bfloat162 v0, v1;
                v0.x = __float2bfloat16_rn(o0.x); v0.y = __float2bfloat16_rn(o0.y);
                v1.x = __float2bfloat16_rn(o1.x); v1.y = __float2bfloat16_rn(o1.y);
                *(__nv_bfloat162*)(dst + (size_t)r0 * HID + d0)       = v0;
                *(__nv_bfloat162*)(dst + (size_t)(r0 + 8) * HID + d0) = v1;
            } else {
                if (resid) {
                    const float2 ra = *(const float2*)(resid + (size_t)r0 * N + col);
                    const float2 rb = *(const float2*)(resid + (size_t)(r0 + 8) * N + col);
                    o0.x += ra.x; o0.y += ra.y;
                    o1.x += rb.x; o1.y += rb.y;
                }
                *(float2*)(C + (size_t)r0 * N + col)       = o0;
                *(float2*)(C + (size_t)(r0 + 8) * N + col) = o1;
            }
        }
    }
}

// ---------------------------------------------------------------------------
// Flash attention, all-bf16 MMA (m16n8k16), 64-key tiles (R13 champion,
// unchanged). Q loaded directly as pre-scaled bf16x2 A-fragments.
// ---------------------------------------------------------------------------
static constexpr int KVSTB = 144;
static constexpr int AKB  = 64 * KVSTB;              // 9216 B per tile
static constexpr int AST  = 2 * AKB;                 // 18432 B per stage
static constexpr int ASMEM = 2 * AST;                // 36864 B

__global__ void __launch_bounds__(256) attn_mma(const __nv_bfloat16* __restrict__ qbf,
                                                const __nv_bfloat16* __restrict__ kbf,
                                                const __nv_bfloat16* __restrict__ vbf,
                                                const float* __restrict__ mask,
                                                __nv_bfloat16* __restrict__ out) {
    extern __shared__ char smem[];
    const uint32_t sb = smem_u32(smem);

    const int tid  = threadIdx.x;
    const int w    = tid >> 5;
    const int lane = tid & 31;
    const int gid  = lane >> 2;
    const int t4   = lane & 3;

    const int q0 = blockIdx.x * 128;
    const int h  = blockIdx.y;
    const int b  = blockIdx.z;

    const int lg = lane >> 3;
    const int lr = lane & 7;
    const int krow = ((lg >> 1) << 3) + lr;
    const int kkof = (lg & 1) * 16;
    const int vkof = (lg & 1) * 8;
    const int vdof = (lg >> 1) * 8;

    const int qr0 = b * SEQ + q0 + w * 16 + gid;
    const __nv_bfloat16* qb0 = qbf + (size_t)qr0 * HID + h * 64;
    const __nv_bfloat16* qb1 = qb0 + (size_t)8 * HID;
    uint32_t aq[4][4];
    #pragma unroll
    for (int ks = 0; ks < 4; ks++) {
        aq[ks][0] = *(const uint32_t*)(qb0 + ks * 16 + 2 * t4);
        aq[ks][1] = *(const uint32_t*)(qb1 + ks * 16 + 2 * t4);
        aq[ks][2] = *(const uint32_t*)(qb0 + ks * 16 + 8 + 2 * t4);
        aq[ks][3] = *(const uint32_t*)(qb1 + ks * 16 + 8 + 2 * t4);
    }

    float l0 = 0.f, l1 = 0.f;
    float acc[8][4];
    #pragma unroll
    for (int i = 0; i < 8; i++)
        #pragma unroll
        for (int q = 0; q < 4; q++) acc[i][q] = 0.f;

    const float* mrow0 = mask + ((size_t)b * SEQ + q0 + w * 16 + gid) * SEQ;
    const float* mrow1 = mrow0 + (size_t)8 * SEQ;

    auto load_kv = [&](int kt, int buf) {
        const int k0 = kt * 64;
        const __nv_bfloat16* srcK = kbf + ((size_t)(b * SEQ + k0)) * HID + h * 64;
        const __nv_bfloat16* srcV = vbf + ((size_t)(b * SEQ + k0)) * HID + h * 64;
        const uint32_t kb = sb + buf * AST;
        const uint32_t vb = kb + AKB;
        #pragma unroll
        for (int i = 0; i < 2; i++) {
            const int idx = tid + i * 256;
            const int row = idx >> 3;
            const int c8  = (idx & 7) * 8;
            CP_ASYNC16(kb + (uint32_t)(row * KVSTB + c8 * 2), srcK + (size_t)row * HID + c8);
            CP_ASYNC16(vb + (uint32_t)(row * KVSTB + c8 * 2), srcV + (size_t)row * HID + c8);
        }
        CP_COMMIT();
    };

    constexpr int NIT = SEQ / 64;
    load_kv(0, 0);

    for (int kt = 0; kt < NIT; kt++) {
        const int buf = kt & 1;
        const int k0  = kt * 64;
        if (kt + 1 < NIT) { load_kv(kt + 1, buf ^ 1); CP_WAIT(1); }
        else              { CP_WAIT(0); }
        __syncthreads();

        const uint32_t kbase = sb + buf * AST;
        const uint32_t vbase = kbase + AKB;

        float sc[8][4];
        #pragma unroll
        for (int nt = 0; nt < 8; nt++)
            #pragma unroll
            for (int q = 0; q < 4; q++) sc[nt][q] = 0.f;

        #pragma unroll
        for (int ks = 0; ks < 4; ks++) {
            #pragma unroll
            for (int ntp = 0; ntp < 4; ntp++) {
                uint32_t r0, r1, r2, r3;
                const uint32_t addr = kbase +
                    (uint32_t)((ntp * 16 + krow) * KVSTB + kkof + ks * 32);
                LDMX4(r0, r1, r2, r3, addr);
                uint32_t b0[2] = {r0, r1}, b1[2] = {r2, r3};
                mma_bf16(sc[2 * ntp],     aq[ks], b0);
                mma_bf16(sc[2 * ntp + 1], aq[ks], b1);
            }
        }

        #pragma unroll
        for (int nt = 0; nt < 8; nt++) {
            const float2 mm0 = *(const float2*)(mrow0 + k0 + nt * 8 + 2 * t4);
            const float2 mm1 = *(const float2*)(mrow1 + k0 + nt * 8 + 2 * t4);
            sc[nt][0] = exp2f(fmaf(mm0.x, LOG2E, sc[nt][0]));
            sc[nt][1] = exp2f(fmaf(mm0.y, LOG2E, sc[nt][1]));
            sc[nt][2] = exp2f(fmaf(mm1.x, LOG2E, sc[nt][2]));
            sc[nt][3] = exp2f(fmaf(mm1.y, LOG2E, sc[nt][3]));
            l0 += sc[nt][0] + sc[nt][1];
            l1 += sc[nt][2] + sc[nt][3];
        }

        #pragma unroll
        for (int j = 0; j < 4; j++) {
            uint32_t pa[4];
            CVT_BF16X2(pa[0], sc[2 * j][1],     sc[2 * j][0]);
            CVT_BF16X2(pa[1], sc[2 * j][3],     sc[2 * j][2]);
            CVT_BF16X2(pa[2], sc[2 * j + 1][1], sc[2 * j + 1][0]);
            CVT_BF16X2(pa[3], sc[2 * j + 1][3], sc[2 * j + 1][2]);
            #pragma unroll
            for (int ndtp = 0; ndtp < 4; ndtp++) {
                uint32_t r0, r1, r2, r3;
                const uint32_t addr = vbase +
                    (uint32_t)((j * 16 + vkof + lr) * KVSTB + (ndtp * 16 + vdof) * 2);
                LDMX4T(r0, r1, r2, r3, addr);
                uint32_t v0[2] = {r0, r1}, v1[2] = {r2, r3};
                mma_bf16(acc[2 * ndtp],     pa, v0);
                mma_bf16(acc[2 * ndtp + 1], pa, v1);
            }
        }
        __syncthreads();
    }

    #pragma unroll
    for (int off = 1; off <= 2; off <<= 1) {
        l0 += __shfl_xor_sync(0xffffffffu, l0, off);
        l1 += __shfl_xor_sync(0xffffffffu, l1, off);
    }
    const float inv0 = 1.f / l0;
    const float inv1 = 1.f / l1;
    __nv_bfloat16* ob0 = out + (size_t)(b * SEQ + q0 + w * 16 + gid) * HID + h * 64;
    __nv_bfloat16* ob1 = ob0 + (size_t)8 * HID;
    #pragma unroll
    for (int ndt = 0; ndt < 8; ndt++) {
        __nv_bfloat162 v0, v1;
        v0.x = __float2bfloat16_rn(acc[ndt][0] * inv0);
        v0.y = __float2bfloat16_rn(acc[ndt][1] * inv0);
        v1.x = __float2bfloat16_rn(acc[ndt][2] * inv1);
        v1.y = __float2bfloat16_rn(acc[ndt][3] * inv1);
        *(__nv_bfloat162*)(ob0 + ndt * 8 + 2 * t4) = v0;
        *(__nv_bfloat162*)(ob1 + ndt * 8 + 2 * t4) = v1;
    }
}

// ---------------------------------------------------------------------------
// Launch
// ---------------------------------------------------------------------------
extern "C" void kernel_launch(void* const* d_in, const int* in_sizes, int n_in,
                              void* d_out, int out_size) {
    const float* hidden = (const float*)d_in[0];
    const float* mask   = (const float*)d_in[1];
    const float* w_qkv  = (const float*)d_in[2];
    const float* b_qkv  = (const float*)d_in[3];
    const float* w_out  = (const float*)d_in[4];
    const float* b_out  = (const float*)d_in[5];
    const float* ln_g   = (const float*)d_in[6];
    const float* ln_b   = (const float*)d_in[7];
    float* out = (float*)d_out;

    __nv_bfloat16 *xln = nullptr, *attnb = nullptr, *wqkvT = nullptr,
                  *woutT = nullptr, *qbfb = nullptr, *kbfb = nullptr, *vbfb = nullptr;
    cudaGetSymbolAddress((void**)&xln,   g_xln);
    cudaGetSymbolAddress((void**)&attnb, g_attn);
    cudaGetSymbolAddress((void**)&wqkvT, g_wqkvT);
    cudaGetSymbolAddress((void**)&woutT, g_woutT);
    cudaGetSymbolAddress((void**)&qbfb,  g_qbf);
    cudaGetSymbolAddress((void**)&kbfb,  g_kbf);
    cudaGetSymbolAddress((void**)&vbfb,  g_vbf);

    cudaFuncSetAttribute(gemm_bf16, cudaFuncAttributeMaxDynamicSharedMemorySize, GSMEM);
    cudaFuncSetAttribute(attn_mma, cudaFuncAttributeMaxDynamicSharedMemorySize, ASMEM);

    ln_kernel<<<ROWS, 256>>>(hidden, ln_g, ln_b, xln);
    transpose_bf<<<dim3(3 * HID / 32, HID / 32), dim3(32, 8)>>>(w_qkv, wqkvT, HID, 3 * HID);
    transpose_bf<<<dim3(HID / 32, HID / 32), dim3(32, 8)>>>(w_out, woutT, HID, HID);

    gemm_bf16<<<dim3(3 * HID / 256, ROWS / 128), 256, GSMEM>>>(
        xln, wqkvT, b_qkv, nullptr, nullptr, qbfb, kbfb, vbfb, ROWS, 3 * HID, HID);

    attn_mma<<<dim3(SEQ / 128, HEADS, BATCH), 256, ASMEM>>>(qbfb, kbfb, vbfb, mask, attnb);

    gemm_bf16<<<dim3(HID / 256, ROWS / 128), 256, GSMEM>>>(
        attnb, woutT, b_out, hidden, out, nullptr, nullptr, nullptr, ROWS, HID, HID);
}

// round 15
// speedup vs baseline: 1.0056x; 1.0056x over previous
#include <cuda_runtime.h>
#include <cuda_bf16.h>
#include <math.h>
#include <stdint.h>

// ---------------------------------------------------------------------------
// LeanSelfAttention, all-bf16 tensor path (fp32 accumulate everywhere):
//   LN(bf16 out) -> QKV (bf16 m16n8k16; Q bf16 pre-scaled, K/V bf16)
//   -> flash attn (bf16 QK^T and P*V, fixed-max exp2 softmax; bf16 out)
//   -> out-proj (bf16 m16n8k16, fp32 bias+residual epilogue)
// R15 = R13 champion + attention grid permuted head-fastest so co-resident
// CTAs share the same mask slice through L2 (512MB -> ~33MB mask DRAM).
// ---------------------------------------------------------------------------

static constexpr int HID   = 1024;
static constexpr int SEQ   = 2048;
static constexpr int BATCH = 2;
static constexpr int ROWS  = BATCH * SEQ;   // 4096
static constexpr int HEADS = 16;
static constexpr float LOG2E = 1.4426950408889634f;

// Scratch (device globals: allocation-free contract)
__device__ __nv_bfloat16 g_xln [ROWS * HID];        // LN output bf16
__device__ __nv_bfloat16 g_qbf[ROWS * HID];         // Q third bf16, PRE-SCALED log2e/8
__device__ __nv_bfloat16 g_kbf[ROWS * HID];         // K third bf16
__device__ __nv_bfloat16 g_vbf[ROWS * HID];         // V third bf16
__device__ __nv_bfloat16 g_attn[ROWS * HID];        // attention output bf16
__device__ __nv_bfloat16 g_wqkvT[3 * HID * HID];    // [N=3072][K=1024] bf16
__device__ __nv_bfloat16 g_woutT[HID * HID];        // [N=1024][K=1024] bf16

// ======================= helpers ======================
__device__ __forceinline__ uint32_t smem_u32(const void* p) {
    uint32_t a;
    asm("{ .reg .u64 t; cvta.to.shared.u64 t, %1; cvt.u32.u64 %0, t; }"
        : "=r"(a) : "l"(p));
    return a;
}
#define CP_ASYNC16(dst, src) \
    asm volatile("cp.async.cg.shared.global [%0], [%1], 16;" :: "r"(dst), "l"(src))
#define CP_COMMIT() asm volatile("cp.async.commit_group;" ::: "memory")
#define CP_WAIT(n)  asm volatile("cp.async.wait_group %0;" :: "n"(n) : "memory")

#define LDMX4(r0, r1, r2, r3, addr) \
    asm volatile("ldmatrix.sync.aligned.m8n8.x4.shared.b16 {%0,%1,%2,%3}, [%4];" \
        : "=r"(r0), "=r"(r1), "=r"(r2), "=r"(r3) : "r"(addr))

#define LDMX4T(r0, r1, r2, r3, addr) \
    asm volatile("ldmatrix.sync.aligned.m8n8.x4.trans.shared.b16 {%0,%1,%2,%3}, [%4];" \
        : "=r"(r0), "=r"(r1), "=r"(r2), "=r"(r3) : "r"(addr))

// pack two f32 -> bf16x2 (hi = first operand, lo = second)
#define CVT_BF16X2(r, hi, lo) \
    asm("cvt.rn.bf16x2.f32 %0, %1, %2;" : "=r"(r) : "f"(hi), "f"(lo))

// m16n8k16 bf16 MMA. D += A*B.
__device__ __forceinline__ void mma_bf16(float* d, const uint32_t* a, const uint32_t* b) {
    asm volatile(
        "mma.sync.aligned.m16n8k16.row.col.f32.bf16.bf16.f32 "
        "{%0,%1,%2,%3}, {%4,%5,%6,%7}, {%8,%9}, {%0,%1,%2,%3};"
        : "+f"(d[0]), "+f"(d[1]), "+f"(d[2]), "+f"(d[3])
        : "r"(a[0]), "r"(a[1]), "r"(a[2]), "r"(a[3]), "r"(b[0]), "r"(b[1]));
}

// ---------------------------------------------------------------------------
// LayerNorm, bf16 output
// ---------------------------------------------------------------------------
__global__ void __launch_bounds__(256) ln_kernel(const float* __restrict__ x,
                                                 const float* __restrict__ g,
                                                 const float* __restrict__ b,
                                                 __nv_bfloat16* __restrict__ y) {
    __shared__ float red[8];
    const int row = blockIdx.x;
    const int t   = threadIdx.x;

    float4 v = ((const float4*)(x + (size_t)row * HID))[t];

    float s = v.x + v.y + v.z + v.w;
    #pragma unroll
    for (int off = 16; off; off >>= 1) s += __shfl_down_sync(0xffffffffu, s, off);
    if ((t & 31) == 0) red[t >> 5] = s;
    __syncthreads();
    if (t < 32) {
        float r = (t < 8) ? red[t] : 0.f;
        #pragma unroll
        for (int off = 4; off; off >>= 1) r += __shfl_down_sync(0xffffffffu, r, off);
        if (t == 0) red[0] = r;
    }
    __syncthreads();
    const float mu = red[0] * (1.f / HID);
    __syncthreads();

    const float dx = v.x - mu, dy = v.y - mu, dz = v.z - mu, dw = v.w - mu;
    float sq = dx * dx + dy * dy + dz * dz + dw * dw;
    #pragma unroll
    for (int off = 16; off; off >>= 1) sq += __shfl_down_sync(0xffffffffu, sq, off);
    if ((t & 31) == 0) red[t >> 5] = sq;
    __syncthreads();
    if (t < 32) {
        float r = (t < 8) ? red[t] : 0.f;
        #pragma unroll
        for (int off = 4; off; off >>= 1) r += __shfl_down_sync(0xffffffffu, r, off);
        if (t == 0) red[0] = r;
    }
    __syncthreads();
    const float inv = rsqrtf(red[0] * (1.f / HID) + 1e-12f);

    const float4 gg = ((const float4*)g)[t];
    const float4 bb = ((const float4*)b)[t];
    __nv_bfloat162 o0, o1;
    o0.x = __float2bfloat16_rn(dx * inv * gg.x + bb.x);
    o0.y = __float2bfloat16_rn(dy * inv * gg.y + bb.y);
    o1.x = __float2bfloat16_rn(dz * inv * gg.z + bb.z);
    o1.y = __float2bfloat16_rn(dw * inv * gg.w + bb.w);
    __nv_bfloat16* yp = y + (size_t)row * HID + t * 4;
    *(__nv_bfloat162*)(yp)     = o0;
    *(__nv_bfloat162*)(yp + 2) = o1;
}

// ---------------------------------------------------------------------------
// Transpose + bf16 convert: in fp32 [R][C] -> out bf16 [C][R]
// ---------------------------------------------------------------------------
__global__ void __launch_bounds__(256) transpose_bf(const float* __restrict__ in,
                                                    __nv_bfloat16* __restrict__ out,
                                                    int R, int C) {
    __shared__ float tile[32][33];
    const int x  = blockIdx.x * 32 + threadIdx.x;
    const int y0 = blockIdx.y * 32;
    #pragma unroll
    for (int j = threadIdx.y; j < 32; j += 8)
        tile[j][threadIdx.x] = in[(size_t)(y0 + j) * C + x];
    __syncthreads();
    const int x2 = y0 + threadIdx.x;
    const int y2 = blockIdx.x * 32;
    #pragma unroll
    for (int j = threadIdx.y; j < 32; j += 8)
        out[(size_t)(y2 + j) * R + x2] = __float2bfloat16_rn(tile[threadIdx.x][j]);
}

// ---------------------------------------------------------------------------
// bf16 m16n8k16 GEMM, 2-stage cp.async pipeline (R13 champion config).
// 128x128 CTA / 64x32 warp, K chunks of 64 bf16 (144B row stride).
// QKV mode: Q third -> qbf bf16 scaled by log2e/8, K -> kbf, V -> vbf.
// ---------------------------------------------------------------------------
static constexpr int GSTB   = 144;                  // smem row stride (bytes)
static constexpr int GTILE  = 128 * GSTB;           // 18432 B per operand tile
static constexpr int GSMEM  = 2 * 2 * GTILE;        // 73728 B

__global__ void __launch_bounds__(256) gemm_bf16(const __nv_bfloat16* __restrict__ A,
                                                 const __nv_bfloat16* __restrict__ Bt,
                                                 const float* __restrict__ bias,
                                                 const float* __restrict__ resid,
                                                 float* __restrict__ C,
                                                 __nv_bfloat16* __restrict__ qbf,
                                                 __nv_bfloat16* __restrict__ kbf,
                                                 __nv_bfloat16* __restrict__ vbf,
                                                 int M, int N, int K) {
    extern __shared__ char smem[];
    const uint32_t sb = smem_u32(smem);

    const int tid  = threadIdx.x;
    const int wid  = tid >> 5;
    const int lane = tid & 31;
    const int gid  = lane >> 2;
    const int t4   = lane & 3;
    const int wm   = wid & 1;
    const int wn   = wid >> 1;
    const int lg   = lane >> 3;
    const int lr   = lane & 7;

    const int m0 = blockIdx.y * 128;
    const int n0 = blockIdx.x * 128;

    const int arow = (lg & 1) * 8 + lr;
    const int akof = (lg >> 1) * 16;
    const int brow = (lg >> 1) * 8 + lr;
    const int bkof = (lg & 1) * 16;

    float acc[4][4][4];
    #pragma unroll
    for (int i = 0; i < 4; i++)
        #pragma unroll
        for (int j = 0; j < 4; j++)
            #pragma unroll
            for (int q = 0; q < 4; q++) acc[i][j][q] = 0.f;

    const int NCH = K >> 6;              // 64-K chunks

    auto load_chunk = [&](int c, int buf) {
        const int kof = c * 64;
        const uint32_t abase = sb + buf * 2 * GTILE;
        const uint32_t bbase = abase + GTILE;
        #pragma unroll
        for (int it = 0; it < 4; it++) {
            const int idx = tid + it * 256;
            const int row = idx >> 3;
            const int c8  = (idx & 7) * 8;
            const uint32_t doff = (uint32_t)(row * GSTB + c8 * 2);
            CP_ASYNC16(abase + doff, A  + (size_t)(m0 + row) * K + kof + c8);
            CP_ASYNC16(bbase + doff, Bt + (size_t)(n0 + row) * K + kof + c8);
        }
        CP_COMMIT();
    };

    load_chunk(0, 0);

    for (int c = 0; c < NCH; c++) {
        const int buf = c & 1;
        if (c + 1 < NCH) { load_chunk(c + 1, buf ^ 1); CP_WAIT(1); }
        else             { CP_WAIT(0); }
        __syncthreads();

        const uint32_t abase = sb + buf * 2 * GTILE;
        const uint32_t bbase = abase + GTILE;

        #pragma unroll
        for (int ks = 0; ks < 4; ks++) {
            uint32_t af[4][4], bf[4][2];
            #pragma unroll
            for (int i = 0; i < 4; i++) {
                const uint32_t addr = abase +
                    (uint32_t)((wm * 64 + i * 16 + arow) * GSTB + akof + ks * 32);
                LDMX4(af[i][0], af[i][1], af[i][2], af[i][3], addr);
            }
            #pragma unroll
            for (int jp = 0; jp < 2; jp++) {
                const uint32_t addr = bbase +
                    (uint32_t)((wn * 32 + jp * 16 + brow) * GSTB + bkof + ks * 32);
                LDMX4(bf[2 * jp][0], bf[2 * jp][1], bf[2 * jp + 1][0], bf[2 * jp + 1][1], addr);
            }
            #pragma unroll
            for (int i = 0; i < 4; i++)
                #pragma unroll
                for (int j = 0; j < 4; j++)
                    mma_bf16(acc[i][j], af[i], bf[j]);
        }
        __syncthreads();
    }

    const bool q_out = (qbf != nullptr) && (n0 < HID);
    const bool k_out = (kbf != nullptr) && (n0 >= HID) && (n0 < 2 * HID);
    const bool v_out = (vbf != nullptr) && (n0 >= 2 * HID);
    const float qscale = 0.125f * LOG2E;

    #pragma unroll
    for (int i = 0; i < 4; i++) {
        const int r0 = m0 + wm * 64 + i * 16 + gid;
        #pragma unroll
        for (int j = 0; j < 4; j++) {
            const int col = n0 + wn * 32 + j * 8 + t4 * 2;
            const float2 bb = *(const float2*)(bias + col);
            float2 o0, o1;
            o0.x = acc[i][j][0] + bb.x;  o0.y = acc[i][j][1] + bb.y;
            o1.x = acc[i][j][2] + bb.x;  o1.y = acc[i][j][3] + bb.y;
            if (q_out || k_out || v_out) {
                __nv_bfloat16* dst = q_out ? qbf : (k_out ? kbf : vbf);
                const int d0 = col - (q_out ? 0 : (k_out ? HID : 2 * HID));
                if (q_out) {
                    o0.x *= qscale; o0.y *= qscale;
                    o1.x *= qscale; o1.y *= qscale;
                }
                __nv_bfloat162 v0, v1;
                v0.x = __float2bfloat16_rn(o0.x); v0.y = __float2bfloat16_rn(o0.y);
                v1.x = __float2bfloat16_rn(o1.x); v1.y = __float2bfloat16_rn(o1.y);
                *(__nv_bfloat162*)(dst + (size_t)r0 * HID + d0)       = v0;
                *(__nv_bfloat162*)(dst + (size_t)(r0 + 8) * HID + d0) = v1;
            } else {
                if (resid) {
                    const float2 ra = *(const float2*)(resid + (size_t)r0 * N + col);
                    const float2 rb = *(const float2*)(resid + (size_t)(r0 + 8) * N + col);
                    o0.x += ra.x; o0.y += ra.y;
                    o1.x += rb.x; o1.y += rb.y;
                }
                *(float2*)(C + (size_t)r0 * N + col)       = o0;
                *(float2*)(C + (size_t)(r0 + 8) * N + col) = o1;
            }
        }
    }
}

// ---------------------------------------------------------------------------
// Flash attention, all-bf16 MMA (m16n8k16), 64-key tiles.
// R15: grid is (head, q-tile, batch) — head fastest — so the 16 CTAs sharing
// one (b, q-tile) mask slice are co-resident and hit L2 on the mask.
// ---------------------------------------------------------------------------
static constexpr int KVSTB = 144;                    // K/V smem row stride (bytes)
static constexpr int AKB  = 64 * KVSTB;              // 9216 B per tile
static constexpr int AST  = 2 * AKB;                 // 18432 B per stage
static constexpr int ASMEM = 2 * AST;                // 36864 B

__global__ void __launch_bounds__(256) attn_mma(const __nv_bfloat16* __restrict__ qbf,
                                                const __nv_bfloat16* __restrict__ kbf,
                                                const __nv_bfloat16* __restrict__ vbf,
                                                const float* __restrict__ mask,
                                                __nv_bfloat16* __restrict__ out) {
    extern __shared__ char smem[];
    const uint32_t sb = smem_u32(smem);

    const int tid  = threadIdx.x;
    const int w    = tid >> 5;
    const int lane = tid & 31;
    const int gid  = lane >> 2;
    const int t4   = lane & 3;

    const int h  = blockIdx.x;                 // head fastest (mask L2 reuse)
    const int q0 = blockIdx.y * 128;
    const int b  = blockIdx.z;

    const int lg = lane >> 3;
    const int lr = lane & 7;
    const int krow = ((lg >> 1) << 3) + lr;
    const int kkof = (lg & 1) * 16;
    const int vkof = (lg & 1) * 8;
    const int vdof = (lg >> 1) * 8;

    // ---- Q bf16 A-fragments: direct loads (pre-scaled in QKV epilogue) ----
    const int qr0 = b * SEQ + q0 + w * 16 + gid;
    const __nv_bfloat16* qb0 = qbf + (size_t)qr0 * HID + h * 64;
    const __nv_bfloat16* qb1 = qb0 + (size_t)8 * HID;
    uint32_t aq[4][4];
    #pragma unroll
    for (int ks = 0; ks < 4; ks++) {
        aq[ks][0] = *(const uint32_t*)(qb0 + ks * 16 + 2 * t4);
        aq[ks][1] = *(const uint32_t*)(qb1 + ks * 16 + 2 * t4);
        aq[ks][2] = *(const uint32_t*)(qb0 + ks * 16 + 8 + 2 * t4);
        aq[ks][3] = *(const uint32_t*)(qb1 + ks * 16 + 8 + 2 * t4);
    }

    float l0 = 0.f, l1 = 0.f;
    float acc[8][4];
    #pragma unroll
    for (int i = 0; i < 8; i++)
        #pragma unroll
        for (int q = 0; q < 4; q++) acc[i][q] = 0.f;

    const float* mrow0 = mask + ((size_t)b * SEQ + q0 + w * 16 + gid) * SEQ;
    const float* mrow1 = mrow0 + (size_t)8 * SEQ;

    auto load_kv = [&](int kt, int buf) {
        const int k0 = kt * 64;
        const __nv_bfloat16* srcK = kbf + ((size_t)(b * SEQ + k0)) * HID + h * 64;
        const __nv_bfloat16* srcV = vbf + ((size_t)(b * SEQ + k0)) * HID + h * 64;
        const uint32_t kb = sb + buf * AST;
        const uint32_t vb = kb + AKB;
        #pragma unroll
        for (int i = 0; i < 2; i++) {
            const int idx = tid + i * 256;
            const int row = idx >> 3;
            const int c8  = (idx & 7) * 8;
            CP_ASYNC16(kb + (uint32_t)(row * KVSTB + c8 * 2), srcK + (size_t)row * HID + c8);
            CP_ASYNC16(vb + (uint32_t)(row * KVSTB + c8 * 2), srcV + (size_t)row * HID + c8);
        }
        CP_COMMIT();
    };

    constexpr int NIT = SEQ / 64;
    load_kv(0, 0);

    for (int kt = 0; kt < NIT; kt++) {
        const int buf = kt & 1;
        const int k0  = kt * 64;
        if (kt + 1 < NIT) { load_kv(kt + 1, buf ^ 1); CP_WAIT(1); }
        else              { CP_WAIT(0); }
        __syncthreads();

        const uint32_t kbase = sb + buf * AST;
        const uint32_t vbase = kbase + AKB;

        float sc[8][4];
        #pragma unroll
        for (int nt = 0; nt < 8; nt++)
            #pragma unroll
            for (int q = 0; q < 4; q++) sc[nt][q] = 0.f;

        #pragma unroll
        for (int ks = 0; ks < 4; ks++) {
            #pragma unroll
            for (int ntp = 0; ntp < 4; ntp++) {
                uint32_t r0, r1, r2, r3;
                const uint32_t addr = kbase +
                    (uint32_t)((ntp * 16 + krow) * KVSTB + kkof + ks * 32);
                LDMX4(r0, r1, r2, r3, addr);
                uint32_t b0[2] = {r0, r1}, b1[2] = {r2, r3};
                mma_bf16(sc[2 * ntp],     aq[ks], b0);
                mma_bf16(sc[2 * ntp + 1], aq[ks], b1);
            }
        }

        #pragma unroll
        for (int nt = 0; nt < 8; nt++) {
            const float2 mm0 = *(const float2*)(mrow0 + k0 + nt * 8 + 2 * t4);
            const float2 mm1 = *(const float2*)(mrow1 + k0 + nt * 8 + 2 * t4);
            sc[nt][0] = exp2f(fmaf(mm0.x, LOG2E, sc[nt][0]));
            sc[nt][1] = exp2f(fmaf(mm0.y, LOG2E, sc[nt][1]));
            sc[nt][2] = exp2f(fmaf(mm1.x, LOG2E, sc[nt][2]));
            sc[nt][3] = exp2f(fmaf(mm1.y, LOG2E, sc[nt][3]));
            l0 += sc[nt][0] + sc[nt][1];
            l1 += sc[nt][2] + sc[nt][3];
        }

        #pragma unroll
        for (int j = 0; j < 4; j++) {
            uint32_t pa[4];
            CVT_BF16X2(pa[0], sc[2 * j][1],     sc[2 * j][0]);
            CVT_BF16X2(pa[1], sc[2 * j][3],     sc[2 * j][2]);
            CVT_BF16X2(pa[2], sc[2 * j + 1][1], sc[2 * j + 1][0]);
            CVT_BF16X2(pa[3], sc[2 * j + 1][3], sc[2 * j + 1][2]);
            #pragma unroll
            for (int ndtp = 0; ndtp < 4; ndtp++) {
                uint32_t r0, r1, r2, r3;
                const uint32_t addr = vbase +
                    (uint32_t)((j * 16 + vkof + lr) * KVSTB + (ndtp * 16 + vdof) * 2);
                LDMX4T(r0, r1, r2, r3, addr);
                uint32_t v0[2] = {r0, r1}, v1[2] = {r2, r3};
                mma_bf16(acc[2 * ndtp],     pa, v0);
                mma_bf16(acc[2 * ndtp + 1], pa, v1);
            }
        }
        __syncthreads();
    }

    #pragma unroll
    for (int off = 1; off <= 2; off <<= 1) {
        l0 += __shfl_xor_sync(0xffffffffu, l0, off);
        l1 += __shfl_xor_sync(0xffffffffu, l1, off);
    }
    const float inv0 = 1.f / l0;
    const float inv1 = 1.f / l1;
    __nv_bfloat16* ob0 = out + (size_t)(b * SEQ + q0 + w * 16 + gid) * HID + h * 64;
    __nv_bfloat16* ob1 = ob0 + (size_t)8 * HID;
    #pragma unroll
    for (int ndt = 0; ndt < 8; ndt++) {
        __nv_bfloat162 v0, v1;
        v0.x = __float2bfloat16_rn(acc[ndt][0] * inv0);
        v0.y = __float2bfloat16_rn(acc[ndt][1] * inv0);
        v1.x = __float2bfloat16_rn(acc[ndt][2] * inv1);
        v1.y = __float2bfloat16_rn(acc[ndt][3] * inv1);
        *(__nv_bfloat162*)(ob0 + ndt * 8 + 2 * t4) = v0;
        *(__nv_bfloat162*)(ob1 + ndt * 8 + 2 * t4) = v1;
    }
}

// ---------------------------------------------------------------------------
// Launch
// ---------------------------------------------------------------------------
extern "C" void kernel_launch(void* const* d_in, const int* in_sizes, int n_in,
                              void* d_out, int out_size) {
    const float* hidden = (const float*)d_in[0];
    const float* mask   = (const float*)d_in[1];
    const float* w_qkv  = (const float*)d_in[2];
    const float* b_qkv  = (const float*)d_in[3];
    const float* w_out  = (const float*)d_in[4];
    const float* b_out  = (const float*)d_in[5];
    const float* ln_g   = (const float*)d_in[6];
    const float* ln_b   = (const float*)d_in[7];
    float* out = (float*)d_out;

    __nv_bfloat16 *xln = nullptr, *attnb = nullptr, *wqkvT = nullptr,
                  *woutT = nullptr, *qbfb = nullptr, *kbfb = nullptr, *vbfb = nullptr;
    cudaGetSymbolAddress((void**)&xln,   g_xln);
    cudaGetSymbolAddress((void**)&attnb, g_attn);
    cudaGetSymbolAddress((void**)&wqkvT, g_wqkvT);
    cudaGetSymbolAddress((void**)&woutT, g_woutT);
    cudaGetSymbolAddress((void**)&qbfb,  g_qbf);
    cudaGetSymbolAddress((void**)&kbfb,  g_kbf);
    cudaGetSymbolAddress((void**)&vbfb,  g_vbf);

    cudaFuncSetAttribute(gemm_bf16, cudaFuncAttributeMaxDynamicSharedMemorySize, GSMEM);
    cudaFuncSetAttribute(attn_mma, cudaFuncAttributeMaxDynamicSharedMemorySize, ASMEM);

    ln_kernel<<<ROWS, 256>>>(hidden, ln_g, ln_b, xln);
    transpose_bf<<<dim3(3 * HID / 32, HID / 32), dim3(32, 8)>>>(w_qkv, wqkvT, HID, 3 * HID);
    transpose_bf<<<dim3(HID / 32, HID / 32), dim3(32, 8)>>>(w_out, woutT, HID, HID);

    gemm_bf16<<<dim3(3 * HID / 128, ROWS / 128), 256, GSMEM>>>(
        xln, wqkvT, b_qkv, nullptr, nullptr, qbfb, kbfb, vbfb, ROWS, 3 * HID, HID);

    attn_mma<<<dim3(HEADS, SEQ / 128, BATCH), 256, ASMEM>>>(qbfb, kbfb, vbfb, mask, attnb);

    gemm_bf16<<<dim3(HID / 128, ROWS / 128), 256, GSMEM>>>(
        attnb, woutT, b_out, hidden, out, nullptr, nullptr, nullptr, ROWS, HID, HID);
}

// round 16
// speedup vs baseline: 1.1106x; 1.1044x over previous
#include <cuda_runtime.h>
#include <cuda_bf16.h>
#include <math.h>
#include <stdint.h>

// ---------------------------------------------------------------------------
// LeanSelfAttention, all-bf16 tensor path (fp32 accumulate everywhere):
//   LN(bf16 out) -> QKV (bf16 m16n8k16; Q bf16 pre-scaled, K/V bf16)
//   -> flash attn (bf16 QK^T and P*V, fixed-max exp2 softmax; bf16 out)
//   -> out-proj (bf16 m16n8k16, fp32 bias+residual epilogue)
// R16 = R13 champion (q-fastest grid) + mask prefetched through the cp.async
// pipeline into smem (removes mask LDG latency from the QK->exp2 chain).
// ---------------------------------------------------------------------------

static constexpr int HID   = 1024;
static constexpr int SEQ   = 2048;
static constexpr int BATCH = 2;
static constexpr int ROWS  = BATCH * SEQ;   // 4096
static constexpr int HEADS = 16;
static constexpr float LOG2E = 1.4426950408889634f;

// Scratch (device globals: allocation-free contract)
__device__ __nv_bfloat16 g_xln [ROWS * HID];        // LN output bf16
__device__ __nv_bfloat16 g_qbf[ROWS * HID];         // Q third bf16, PRE-SCALED log2e/8
__device__ __nv_bfloat16 g_kbf[ROWS * HID];         // K third bf16
__device__ __nv_bfloat16 g_vbf[ROWS * HID];         // V third bf16
__device__ __nv_bfloat16 g_attn[ROWS * HID];        // attention output bf16
__device__ __nv_bfloat16 g_wqkvT[3 * HID * HID];    // [N=3072][K=1024] bf16
__device__ __nv_bfloat16 g_woutT[HID * HID];        // [N=1024][K=1024] bf16

// ======================= helpers ======================
__device__ __forceinline__ uint32_t smem_u32(const void* p) {
    uint32_t a;
    asm("{ .reg .u64 t; cvta.to.shared.u64 t, %1; cvt.u32.u64 %0, t; }"
        : "=r"(a) : "l"(p));
    return a;
}
#define CP_ASYNC16(dst, src) \
    asm volatile("cp.async.cg.shared.global [%0], [%1], 16;" :: "r"(dst), "l"(src))
#define CP_COMMIT() asm volatile("cp.async.commit_group;" ::: "memory")
#define CP_WAIT(n)  asm volatile("cp.async.wait_group %0;" :: "n"(n) : "memory")

#define LDMX4(r0, r1, r2, r3, addr) \
    asm volatile("ldmatrix.sync.aligned.m8n8.x4.shared.b16 {%0,%1,%2,%3}, [%4];" \
        : "=r"(r0), "=r"(r1), "=r"(r2), "=r"(r3) : "r"(addr))

#define LDMX4T(r0, r1, r2, r3, addr) \
    asm volatile("ldmatrix.sync.aligned.m8n8.x4.trans.shared.b16 {%0,%1,%2,%3}, [%4];" \
        : "=r"(r0), "=r"(r1), "=r"(r2), "=r"(r3) : "r"(addr))

// pack two f32 -> bf16x2 (hi = first operand, lo = second)
#define CVT_BF16X2(r, hi, lo) \
    asm("cvt.rn.bf16x2.f32 %0, %1, %2;" : "=r"(r) : "f"(hi), "f"(lo))

// m16n8k16 bf16 MMA. D += A*B.
__device__ __forceinline__ void mma_bf16(float* d, const uint32_t* a, const uint32_t* b) {
    asm volatile(
        "mma.sync.aligned.m16n8k16.row.col.f32.bf16.bf16.f32 "
        "{%0,%1,%2,%3}, {%4,%5,%6,%7}, {%8,%9}, {%0,%1,%2,%3};"
        : "+f"(d[0]), "+f"(d[1]), "+f"(d[2]), "+f"(d[3])
        : "r"(a[0]), "r"(a[1]), "r"(a[2]), "r"(a[3]), "r"(b[0]), "r"(b[1]));
}

// ---------------------------------------------------------------------------
// LayerNorm, bf16 output
// ---------------------------------------------------------------------------
__global__ void __launch_bounds__(256) ln_kernel(const float* __restrict__ x,
                                                 const float* __restrict__ g,
                                                 const float* __restrict__ b,
                                                 __nv_bfloat16* __restrict__ y) {
    __shared__ float red[8];
    const int row = blockIdx.x;
    const int t   = threadIdx.x;

    float4 v = ((const float4*)(x + (size_t)row * HID))[t];

    float s = v.x + v.y + v.z + v.w;
    #pragma unroll
    for (int off = 16; off; off >>= 1) s += __shfl_down_sync(0xffffffffu, s, off);
    if ((t & 31) == 0) red[t >> 5] = s;
    __syncthreads();
    if (t < 32) {
        float r = (t < 8) ? red[t] : 0.f;
        #pragma unroll
        for (int off = 4; off; off >>= 1) r += __shfl_down_sync(0xffffffffu, r, off);
        if (t == 0) red[0] = r;
    }
    __syncthreads();
    const float mu = red[0] * (1.f / HID);
    __syncthreads();

    const float dx = v.x - mu, dy = v.y - mu, dz = v.z - mu, dw = v.w - mu;
    float sq = dx * dx + dy * dy + dz * dz + dw * dw;
    #pragma unroll
    for (int off = 16; off; off >>= 1) sq += __shfl_down_sync(0xffffffffu, sq, off);
    if ((t & 31) == 0) red[t >> 5] = sq;
    __syncthreads();
    if (t < 32) {
        float r = (t < 8) ? red[t] : 0.f;
        #pragma unroll
        for (int off = 4; off; off >>= 1) r += __shfl_down_sync(0xffffffffu, r, off);
        if (t == 0) red[0] = r;
    }
    __syncthreads();
    const float inv = rsqrtf(red[0] * (1.f / HID) + 1e-12f);

    const float4 gg = ((const float4*)g)[t];
    const float4 bb = ((const float4*)b)[t];
    __nv_bfloat162 o0, o1;
    o0.x = __float2bfloat16_rn(dx * inv * gg.x + bb.x);
    o0.y = __float2bfloat16_rn(dy * inv * gg.y + bb.y);
    o1.x = __float2bfloat16_rn(dz * inv * gg.z + bb.z);
    o1.y = __float2bfloat16_rn(dw * inv * gg.w + bb.w);
    __nv_bfloat16* yp = y + (size_t)row * HID + t * 4;
    *(__nv_bfloat162*)(yp)     = o0;
    *(__nv_bfloat162*)(yp + 2) = o1;
}

// ---------------------------------------------------------------------------
// Transpose + bf16 convert: in fp32 [R][C] -> out bf16 [C][R]
// ---------------------------------------------------------------------------
__global__ void __launch_bounds__(256) transpose_bf(const float* __restrict__ in,
                                                    __nv_bfloat16* __restrict__ out,
                                                    int R, int C) {
    __shared__ float tile[32][33];
    const int x  = blockIdx.x * 32 + threadIdx.x;
    const int y0 = blockIdx.y * 32;
    #pragma unroll
    for (int j = threadIdx.y; j < 32; j += 8)
        tile[j][threadIdx.x] = in[(size_t)(y0 + j) * C + x];
    __syncthreads();
    const int x2 = y0 + threadIdx.x;
    const int y2 = blockIdx.x * 32;
    #pragma unroll
    for (int j = threadIdx.y; j < 32; j += 8)
        out[(size_t)(y2 + j) * R + x2] = __float2bfloat16_rn(tile[threadIdx.x][j]);
}

// ---------------------------------------------------------------------------
// bf16 m16n8k16 GEMM, 2-stage cp.async pipeline (R13 champion config).
// 128x128 CTA / 64x32 warp, K chunks of 64 bf16 (144B row stride).
// QKV mode: Q third -> qbf bf16 scaled by log2e/8, K -> kbf, V -> vbf.
// ---------------------------------------------------------------------------
static constexpr int GSTB   = 144;                  // smem row stride (bytes)
static constexpr int GTILE  = 128 * GSTB;           // 18432 B per operand tile
static constexpr int GSMEM  = 2 * 2 * GTILE;        // 73728 B

__global__ void __launch_bounds__(256) gemm_bf16(const __nv_bfloat16* __restrict__ A,
                                                 const __nv_bfloat16* __restrict__ Bt,
                                                 const float* __restrict__ bias,
                                                 const float* __restrict__ resid,
                                                 float* __restrict__ C,
                                                 __nv_bfloat16* __restrict__ qbf,
                                                 __nv_bfloat16* __restrict__ kbf,
                                                 __nv_bfloat16* __restrict__ vbf,
                                                 int M, int N, int K) {
    extern __shared__ char smem[];
    const uint32_t sb = smem_u32(smem);

    const int tid  = threadIdx.x;
    const int wid  = tid >> 5;
    const int lane = tid & 31;
    const int gid  = lane >> 2;
    const int t4   = lane & 3;
    const int wm   = wid & 1;
    const int wn   = wid >> 1;
    const int lg   = lane >> 3;
    const int lr   = lane & 7;

    const int m0 = blockIdx.y * 128;
    const int n0 = blockIdx.x * 128;

    const int arow = (lg & 1) * 8 + lr;
    const int akof = (lg >> 1) * 16;
    const int brow = (lg >> 1) * 8 + lr;
    const int bkof = (lg & 1) * 16;

    float acc[4][4][4];
    #pragma unroll
    for (int i = 0; i < 4; i++)
        #pragma unroll
        for (int j = 0; j < 4; j++)
            #pragma unroll
            for (int q = 0; q < 4; q++) acc[i][j][q] = 0.f;

    const int NCH = K >> 6;              // 64-K chunks

    auto load_chunk = [&](int c, int buf) {
        const int kof = c * 64;
        const uint32_t abase = sb + buf * 2 * GTILE;
        const uint32_t bbase = abase + GTILE;
        #pragma unroll
        for (int it = 0; it < 4; it++) {
            const int idx = tid + it * 256;
            const int row = idx >> 3;
            const int c8  = (idx & 7) * 8;
            const uint32_t doff = (uint32_t)(row * GSTB + c8 * 2);
            CP_ASYNC16(abase + doff, A  + (size_t)(m0 + row) * K + kof + c8);
            CP_ASYNC16(bbase + doff, Bt + (size_t)(n0 + row) * K + kof + c8);
        }
        CP_COMMIT();
    };

    load_chunk(0, 0);

    for (int c = 0; c < NCH; c++) {
        const int buf = c & 1;
        if (c + 1 < NCH) { load_chunk(c + 1, buf ^ 1); CP_WAIT(1); }
        else             { CP_WAIT(0); }
        __syncthreads();

        const uint32_t abase = sb + buf * 2 * GTILE;
        const uint32_t bbase = abase + GTILE;

        #pragma unroll
        for (int ks = 0; ks < 4; ks++) {
            uint32_t af[4][4], bf[4][2];
            #pragma unroll
            for (int i = 0; i < 4; i++) {
                const uint32_t addr = abase +
                    (uint32_t)((wm * 64 + i * 16 + arow) * GSTB + akof + ks * 32);
                LDMX4(af[i][0], af[i][1], af[i][2], af[i][3], addr);
            }
            #pragma unroll
            for (int jp = 0; jp < 2; jp++) {
                const uint32_t addr = bbase +
                    (uint32_t)((wn * 32 + jp * 16 + brow) * GSTB + bkof + ks * 32);
                LDMX4(bf[2 * jp][0], bf[2 * jp][1], bf[2 * jp + 1][0], bf[2 * jp + 1][1], addr);
            }
            #pragma unroll
            for (int i = 0; i < 4; i++)
                #pragma unroll
                for (int j = 0; j < 4; j++)
                    mma_bf16(acc[i][j], af[i], bf[j]);
        }
        __syncthreads();
    }

    const bool q_out = (qbf != nullptr) && (n0 < HID);
    const bool k_out = (kbf != nullptr) && (n0 >= HID) && (n0 < 2 * HID);
    const bool v_out = (vbf != nullptr) && (n0 >= 2 * HID);
    const float qscale = 0.125f * LOG2E;

    #pragma unroll
    for (int i = 0; i < 4; i++) {
        const int r0 = m0 + wm * 64 + i * 16 + gid;
        #pragma unroll
        for (int j = 0; j < 4; j++) {
            const int col = n0 + wn * 32 + j * 8 + t4 * 2;
            const float2 bb = *(const float2*)(bias + col);
            float2 o0, o1;
            o0.x = acc[i][j][0] + bb.x;  o0.y = acc[i][j][1] + bb.y;
            o1.x = acc[i][j][2] + bb.x;  o1.y = acc[i][j][3] + bb.y;
            if (q_out || k_out || v_out) {
                __nv_bfloat16* dst = q_out ? qbf : (k_out ? kbf : vbf);
                const int d0 = col - (q_out ? 0 : (k_out ? HID : 2 * HID));
                if (q_out) {
                    o0.x *= qscale; o0.y *= qscale;
                    o1.x *= qscale; o1.y *= qscale;
                }
                __nv_bfloat162 v0, v1;
                v0.x = __float2bfloat16_rn(o0.x); v0.y = __float2bfloat16_rn(o0.y);
                v1.x = __float2bfloat16_rn(o1.x); v1.y = __float2bfloat16_rn(o1.y);
                *(__nv_bfloat162*)(dst + (size_t)r0 * HID + d0)       = v0;
                *(__nv_bfloat162*)(dst + (size_t)(r0 + 8) * HID + d0) = v1;
            } else {
                if (resid) {
                    const float2 ra = *(const float2*)(resid + (size_t)r0 * N + col);
                    const float2 rb = *(const float2*)(resid + (size_t)(r0 + 8) * N + col);
                    o0.x += ra.x; o0.y += ra.y;
                    o1.x += rb.x; o1.y += rb.y;
                }
                *(float2*)(C + (size_t)r0 * N + col)       = o0;
                *(float2*)(C + (size_t)(r0 + 8) * N + col) = o1;
            }
        }
    }
}

// ---------------------------------------------------------------------------
// Flash attention, all-bf16 MMA (m16n8k16), 64-key tiles, q-fastest grid.
// R16: mask tile prefetched via cp.async into smem (rows padded to 68 floats)
// so the exp2 phase reads LDS instead of in-loop LDG.
// ---------------------------------------------------------------------------
static constexpr int KVSTB = 144;                    // K/V smem row stride (bytes)
static constexpr int AKB   = 64 * KVSTB;             // 9216 B per K or V tile
static constexpr int AST   = 2 * AKB;                // K+V per stage: 18432 B
static constexpr int MSTF  = 68;                     // mask row stride (floats)
static constexpr int MKB   = 128 * MSTF * 4;         // 34816 B mask tile per stage
static constexpr int ASMEM = 2 * AST + 2 * MKB;      // 106496 B

__global__ void __launch_bounds__(256) attn_mma(const __nv_bfloat16* __restrict__ qbf,
                                                const __nv_bfloat16* __restrict__ kbf,
                                                const __nv_bfloat16* __restrict__ vbf,
                                                const float* __restrict__ mask,
                                                __nv_bfloat16* __restrict__ out) {
    extern __shared__ char smem[];
    const uint32_t sb = smem_u32(smem);

    const int tid  = threadIdx.x;
    const int w    = tid >> 5;
    const int lane = tid & 31;
    const int gid  = lane >> 2;
    const int t4   = lane & 3;

    const int q0 = blockIdx.x * 128;                 // q-tile fastest (R13 grid)
    const int h  = blockIdx.y;
    const int b  = blockIdx.z;

    const int lg = lane >> 3;
    const int lr = lane & 7;
    const int krow = ((lg >> 1) << 3) + lr;
    const int kkof = (lg & 1) * 16;
    const int vkof = (lg & 1) * 8;
    const int vdof = (lg >> 1) * 8;

    // ---- Q bf16 A-fragments: direct loads (pre-scaled in QKV epilogue) ----
    const int qr0 = b * SEQ + q0 + w * 16 + gid;
    const __nv_bfloat16* qb0 = qbf + (size_t)qr0 * HID + h * 64;
    const __nv_bfloat16* qb1 = qb0 + (size_t)8 * HID;
    uint32_t aq[4][4];
    #pragma unroll
    for (int ks = 0; ks < 4; ks++) {
        aq[ks][0] = *(const uint32_t*)(qb0 + ks * 16 + 2 * t4);
        aq[ks][1] = *(const uint32_t*)(qb1 + ks * 16 + 2 * t4);
        aq[ks][2] = *(const uint32_t*)(qb0 + ks * 16 + 8 + 2 * t4);
        aq[ks][3] = *(const uint32_t*)(qb1 + ks * 16 + 8 + 2 * t4);
    }

    float l0 = 0.f, l1 = 0.f;
    float acc[8][4];
    #pragma unroll
    for (int i = 0; i < 8; i++)
        #pragma unroll
        for (int q = 0; q < 4; q++) acc[i][q] = 0.f;

    const float* mbase = mask + ((size_t)b * SEQ + q0) * SEQ;   // [128 rows][SEQ]

    auto load_kv = [&](int kt, int buf) {
        const int k0 = kt * 64;
        const __nv_bfloat16* srcK = kbf + ((size_t)(b * SEQ + k0)) * HID + h * 64;
        const __nv_bfloat16* srcV = vbf + ((size_t)(b * SEQ + k0)) * HID + h * 64;
        const uint32_t kb = sb + buf * AST;
        const uint32_t vb = kb + AKB;
        const uint32_t mb = sb + 2 * AST + buf * MKB;
        #pragma unroll
        for (int i = 0; i < 2; i++) {                 // K/V: 512 16B chunks each
            const int idx = tid + i * 256;
            const int row = idx >> 3;
            const int c8  = (idx & 7) * 8;
            CP_ASYNC16(kb + (uint32_t)(row * KVSTB + c8 * 2), srcK + (size_t)row * HID + c8);
            CP_ASYNC16(vb + (uint32_t)(row * KVSTB + c8 * 2), srcV + (size_t)row * HID + c8);
        }
        #pragma unroll
        for (int i = 0; i < 8; i++) {                 // mask: 2048 16B chunks
            const int idx = tid + i * 256;
            const int row = idx >> 4;                 // 0..127 (q row)
            const int c4  = (idx & 15) << 2;          // float col 0..60
            CP_ASYNC16(mb + (uint32_t)(row * MSTF + c4) * 4,
                       mbase + (size_t)row * SEQ + k0 + c4);
        }
        CP_COMMIT();
    };

    constexpr int NIT = SEQ / 64;
    load_kv(0, 0);

    for (int kt = 0; kt < NIT; kt++) {
        const int buf = kt & 1;
        if (kt + 1 < NIT) { load_kv(kt + 1, buf ^ 1); CP_WAIT(1); }
        else              { CP_WAIT(0); }
        __syncthreads();

        const uint32_t kbase = sb + buf * AST;
        const uint32_t vbase = kbase + AKB;
        const float*   Ms    = (const float*)(smem + 2 * AST + buf * MKB);
        const float*   ms0   = Ms + (w * 16 + gid) * MSTF + 2 * t4;
        const float*   ms1   = ms0 + 8 * MSTF;

        float sc[8][4];
        #pragma unroll
        for (int nt = 0; nt < 8; nt++)
            #pragma unroll
            for (int q = 0; q < 4; q++) sc[nt][q] = 0.f;

        #pragma unroll
        for (int ks = 0; ks < 4; ks++) {
            #pragma unroll
            for (int ntp = 0; ntp < 4; ntp++) {
                uint32_t r0, r1, r2, r3;
                const uint32_t addr = kbase +
                    (uint32_t)((ntp * 16 + krow) * KVSTB + kkof + ks * 32);
                LDMX4(r0, r1, r2, r3, addr);
                uint32_t b0[2] = {r0, r1}, b1[2] = {r2, r3};
                mma_bf16(sc[2 * ntp],     aq[ks], b0);
                mma_bf16(sc[2 * ntp + 1], aq[ks], b1);
            }
        }

        #pragma unroll
        for (int nt = 0; nt < 8; nt++) {
            const float2 mm0 = *(const float2*)(ms0 + nt * 8);
            const float2 mm1 = *(const float2*)(ms1 + nt * 8);
            sc[nt][0] = exp2f(fmaf(mm0.x, LOG2E, sc[nt][0]));
            sc[nt][1] = exp2f(fmaf(mm0.y, LOG2E, sc[nt][1]));
            sc[nt][2] = exp2f(fmaf(mm1.x, LOG2E, sc[nt][2]));
            sc[nt][3] = exp2f(fmaf(mm1.y, LOG2E, sc[nt][3]));
            l0 += sc[nt][0] + sc[nt][1];
            l1 += sc[nt][2] + sc[nt][3];
        }

        #pragma unroll
        for (int j = 0; j < 4; j++) {
            uint32_t pa[4];
            CVT_BF16X2(pa[0], sc[2 * j][1],     sc[2 * j][0]);
            CVT_BF16X2(pa[1], sc[2 * j][3],     sc[2 * j][2]);
            CVT_BF16X2(pa[2], sc[2 * j + 1][1], sc[2 * j + 1][0]);
            CVT_BF16X2(pa[3], sc[2 * j + 1][3], sc[2 * j + 1][2]);
            #pragma unroll
            for (int ndtp = 0; ndtp < 4; ndtp++) {
                uint32_t r0, r1, r2, r3;
                const uint32_t addr = vbase +
                    (uint32_t)((j * 16 + vkof + lr) * KVSTB + (ndtp * 16 + vdof) * 2);
                LDMX4T(r0, r1, r2, r3, addr);
                uint32_t v0[2] = {r0, r1}, v1[2] = {r2, r3};
                mma_bf16(acc[2 * ndtp],     pa, v0);
                mma_bf16(acc[2 * ndtp + 1], pa, v1);
            }
        }
        __syncthreads();
    }

    #pragma unroll
    for (int off = 1; off <= 2; off <<= 1) {
        l0 += __shfl_xor_sync(0xffffffffu, l0, off);
        l1 += __shfl_xor_sync(0xffffffffu, l1, off);
    }
    const float inv0 = 1.f / l0;
    const float inv1 = 1.f / l1;
    __nv_bfloat16* ob0 = out + (size_t)(b * SEQ + q0 + w * 16 + gid) * HID + h * 64;
    __nv_bfloat16* ob1 = ob0 + (size_t)8 * HID;
    #pragma unroll
    for (int ndt = 0; ndt < 8; ndt++) {
        __nv_bfloat162 v0, v1;
        v0.x = __float2bfloat16_rn(acc[ndt][0] * inv0);
        v0.y = __float2bfloat16_rn(acc[ndt][1] * inv0);
        v1.x = __float2bfloat16_rn(acc[ndt][2] * inv1);
        v1.y = __float2bfloat16_rn(acc[ndt][3] * inv1);
        *(__nv_bfloat162*)(ob0 + ndt * 8 + 2 * t4) = v0;
        *(__nv_bfloat162*)(ob1 + ndt * 8 + 2 * t4) = v1;
    }
}

// ---------------------------------------------------------------------------
// Launch
// ---------------------------------------------------------------------------
extern "C" void kernel_launch(void* const* d_in, const int* in_sizes, int n_in,
                              void* d_out, int out_size) {
    const float* hidden = (const float*)d_in[0];
    const float* mask   = (const float*)d_in[1];
    const float* w_qkv  = (const float*)d_in[2];
    const float* b_qkv  = (const float*)d_in[3];
    const float* w_out  = (const float*)d_in[4];
    const float* b_out  = (const float*)d_in[5];
    const float* ln_g   = (const float*)d_in[6];
    const float* ln_b   = (const float*)d_in[7];
    float* out = (float*)d_out;

    __nv_bfloat16 *xln = nullptr, *attnb = nullptr, *wqkvT = nullptr,
                  *woutT = nullptr, *qbfb = nullptr, *kbfb = nullptr, *vbfb = nullptr;
    cudaGetSymbolAddress((void**)&xln,   g_xln);
    cudaGetSymbolAddress((void**)&attnb, g_attn);
    cudaGetSymbolAddress((void**)&wqkvT, g_wqkvT);
    cudaGetSymbolAddress((void**)&woutT, g_woutT);
    cudaGetSymbolAddress((void**)&qbfb,  g_qbf);
    cudaGetSymbolAddress((void**)&kbfb,  g_kbf);
    cudaGetSymbolAddress((void**)&vbfb,  g_vbf);

    cudaFuncSetAttribute(gemm_bf16, cudaFuncAttributeMaxDynamicSharedMemorySize, GSMEM);
    cudaFuncSetAttribute(attn_mma, cudaFuncAttributeMaxDynamicSharedMemorySize, ASMEM);

    ln_kernel<<<ROWS, 256>>>(hidden, ln_g, ln_b, xln);
    transpose_bf<<<dim3(3 * HID / 32, HID / 32), dim3(32, 8)>>>(w_qkv, wqkvT, HID, 3 * HID);
    transpose_bf<<<dim3(HID / 32, HID / 32), dim3(32, 8)>>>(w_out, woutT, HID, HID);

    gemm_bf16<<<dim3(3 * HID / 128, ROWS / 128), 256, GSMEM>>>(
        xln, wqkvT, b_qkv, nullptr, nullptr, qbfb, kbfb, vbfb, ROWS, 3 * HID, HID);

    attn_mma<<<dim3(SEQ / 128, HEADS, BATCH), 256, ASMEM>>>(qbfb, kbfb, vbfb, mask, attnb);

    gemm_bf16<<<dim3(HID / 128, ROWS / 128), 256, GSMEM>>>(
        attnb, woutT, b_out, hidden, out, nullptr, nullptr, nullptr, ROWS, HID, HID);
}

// round 17
// speedup vs baseline: 1.1743x; 1.0573x over previous
#include <cuda_runtime.h>
#include <cuda_bf16.h>
#include <math.h>
#include <stdint.h>

// ---------------------------------------------------------------------------
// LeanSelfAttention, all-bf16 tensor path (fp32 accumulate everywhere):
//   LN(bf16 out) -> QKV (bf16 m16n8k16; Q bf16 pre-scaled, K/V bf16)
//   -> flash attn (bf16 QK^T and P*V, fixed-max exp2 softmax; bf16 out)
//   -> out-proj (bf16 m16n8k16, fp32 bias+residual epilogue)
// R17 = R16 + mask pre-converted once to bf16*log2e (halves the mask L2
// stream that now bounds the attention mainloop).
// ---------------------------------------------------------------------------

static constexpr int HID   = 1024;
static constexpr int SEQ   = 2048;
static constexpr int BATCH = 2;
static constexpr int ROWS  = BATCH * SEQ;   // 4096
static constexpr int HEADS = 16;
static constexpr float LOG2E = 1.4426950408889634f;

// Scratch (device globals: allocation-free contract)
__device__ __nv_bfloat16 g_xln [ROWS * HID];        // LN output bf16
__device__ __nv_bfloat16 g_qbf[ROWS * HID];         // Q third bf16, PRE-SCALED log2e/8
__device__ __nv_bfloat16 g_kbf[ROWS * HID];         // K third bf16
__device__ __nv_bfloat16 g_vbf[ROWS * HID];         // V third bf16
__device__ __nv_bfloat16 g_attn[ROWS * HID];        // attention output bf16
__device__ __nv_bfloat16 g_wqkvT[3 * HID * HID];    // [N=3072][K=1024] bf16
__device__ __nv_bfloat16 g_woutT[HID * HID];        // [N=1024][K=1024] bf16
__device__ __nv_bfloat16 g_mbf [BATCH * SEQ * SEQ]; // mask * log2e, bf16

// ======================= helpers ======================
__device__ __forceinline__ uint32_t smem_u32(const void* p) {
    uint32_t a;
    asm("{ .reg .u64 t; cvta.to.shared.u64 t, %1; cvt.u32.u64 %0, t; }"
        : "=r"(a) : "l"(p));
    return a;
}
#define CP_ASYNC16(dst, src) \
    asm volatile("cp.async.cg.shared.global [%0], [%1], 16;" :: "r"(dst), "l"(src))
#define CP_COMMIT() asm volatile("cp.async.commit_group;" ::: "memory")
#define CP_WAIT(n)  asm volatile("cp.async.wait_group %0;" :: "n"(n) : "memory")

#define LDMX4(r0, r1, r2, r3, addr) \
    asm volatile("ldmatrix.sync.aligned.m8n8.x4.shared.b16 {%0,%1,%2,%3}, [%4];" \
        : "=r"(r0), "=r"(r1), "=r"(r2), "=r"(r3) : "r"(addr))

#define LDMX4T(r0, r1, r2, r3, addr) \
    asm volatile("ldmatrix.sync.aligned.m8n8.x4.trans.shared.b16 {%0,%1,%2,%3}, [%4];" \
        : "=r"(r0), "=r"(r1), "=r"(r2), "=r"(r3) : "r"(addr))

// pack two f32 -> bf16x2 (hi = first operand, lo = second)
#define CVT_BF16X2(r, hi, lo) \
    asm("cvt.rn.bf16x2.f32 %0, %1, %2;" : "=r"(r) : "f"(hi), "f"(lo))

// m16n8k16 bf16 MMA. D += A*B.
__device__ __forceinline__ void mma_bf16(float* d, const uint32_t* a, const uint32_t* b) {
    asm volatile(
        "mma.sync.aligned.m16n8k16.row.col.f32.bf16.bf16.f32 "
        "{%0,%1,%2,%3}, {%4,%5,%6,%7}, {%8,%9}, {%0,%1,%2,%3};"
        : "+f"(d[0]), "+f"(d[1]), "+f"(d[2]), "+f"(d[3])
        : "r"(a[0]), "r"(a[1]), "r"(a[2]), "r"(a[3]), "r"(b[0]), "r"(b[1]));
}

// ---------------------------------------------------------------------------
// LayerNorm, bf16 output
// ---------------------------------------------------------------------------
__global__ void __launch_bounds__(256) ln_kernel(const float* __restrict__ x,
                                                 const float* __restrict__ g,
                                                 const float* __restrict__ b,
                                                 __nv_bfloat16* __restrict__ y) {
    __shared__ float red[8];
    const int row = blockIdx.x;
    const int t   = threadIdx.x;

    float4 v = ((const float4*)(x + (size_t)row * HID))[t];

    float s = v.x + v.y + v.z + v.w;
    #pragma unroll
    for (int off = 16; off; off >>= 1) s += __shfl_down_sync(0xffffffffu, s, off);
    if ((t & 31) == 0) red[t >> 5] = s;
    __syncthreads();
    if (t < 32) {
        float r = (t < 8) ? red[t] : 0.f;
        #pragma unroll
        for (int off = 4; off; off >>= 1) r += __shfl_down_sync(0xffffffffu, r, off);
        if (t == 0) red[0] = r;
    }
    __syncthreads();
    const float mu = red[0] * (1.f / HID);
    __syncthreads();

    const float dx = v.x - mu, dy = v.y - mu, dz = v.z - mu, dw = v.w - mu;
    float sq = dx * dx + dy * dy + dz * dz + dw * dw;
    #pragma unroll
    for (int off = 16; off; off >>= 1) sq += __shfl_down_sync(0xffffffffu, sq, off);
    if ((t & 31) == 0) red[t >> 5] = sq;
    __syncthreads();
    if (t < 32) {
        float r = (t < 8) ? red[t] : 0.f;
        #pragma unroll
        for (int off = 4; off; off >>= 1) r += __shfl_down_sync(0xffffffffu, r, off);
        if (t == 0) red[0] = r;
    }
    __syncthreads();
    const float inv = rsqrtf(red[0] * (1.f / HID) + 1e-12f);

    const float4 gg = ((const float4*)g)[t];
    const float4 bb = ((const float4*)b)[t];
    __nv_bfloat162 o0, o1;
    o0.x = __float2bfloat16_rn(dx * inv * gg.x + bb.x);
    o0.y = __float2bfloat16_rn(dy * inv * gg.y + bb.y);
    o1.x = __float2bfloat16_rn(dz * inv * gg.z + bb.z);
    o1.y = __float2bfloat16_rn(dw * inv * gg.w + bb.w);
    __nv_bfloat16* yp = y + (size_t)row * HID + t * 4;
    *(__nv_bfloat162*)(yp)     = o0;
    *(__nv_bfloat162*)(yp + 2) = o1;
}

// ---------------------------------------------------------------------------
// Mask pre-convert: mbf[i] = bf16(mask[i] * log2e)
// ---------------------------------------------------------------------------
__global__ void __launch_bounds__(256) mask_bf(const float* __restrict__ mask,
                                               __nv_bfloat16* __restrict__ mbf) {
    const size_t i = ((size_t)blockIdx.x * 256 + threadIdx.x) * 4;
    const float4 m = *(const float4*)(mask + i);
    __nv_bfloat162 o0, o1;
    o0.x = __float2bfloat16_rn(m.x * LOG2E);
    o0.y = __float2bfloat16_rn(m.y * LOG2E);
    o1.x = __float2bfloat16_rn(m.z * LOG2E);
    o1.y = __float2bfloat16_rn(m.w * LOG2E);
    *(__nv_bfloat162*)(mbf + i)     = o0;
    *(__nv_bfloat162*)(mbf + i + 2) = o1;
}

// ---------------------------------------------------------------------------
// Transpose + bf16 convert: in fp32 [R][C] -> out bf16 [C][R]
// ---------------------------------------------------------------------------
__global__ void __launch_bounds__(256) transpose_bf(const float* __restrict__ in,
                                                    __nv_bfloat16* __restrict__ out,
                                                    int R, int C) {
    __shared__ float tile[32][33];
    const int x  = blockIdx.x * 32 + threadIdx.x;
    const int y0 = blockIdx.y * 32;
    #pragma unroll
    for (int j = threadIdx.y; j < 32; j += 8)
        tile[j][threadIdx.x] = in[(size_t)(y0 + j) * C + x];
    __syncthreads();
    const int x2 = y0 + threadIdx.x;
    const int y2 = blockIdx.x * 32;
    #pragma unroll
    for (int j = threadIdx.y; j < 32; j += 8)
        out[(size_t)(y2 + j) * R + x2] = __float2bfloat16_rn(tile[threadIdx.x][j]);
}

// ---------------------------------------------------------------------------
// bf16 m16n8k16 GEMM, 2-stage cp.async pipeline (champion config).
// ---------------------------------------------------------------------------
static constexpr int GSTB   = 144;                  // smem row stride (bytes)
static constexpr int GTILE  = 128 * GSTB;           // 18432 B per operand tile
static constexpr int GSMEM  = 2 * 2 * GTILE;        // 73728 B

__global__ void __launch_bounds__(256) gemm_bf16(const __nv_bfloat16* __restrict__ A,
                                                 const __nv_bfloat16* __restrict__ Bt,
                                                 const float* __restrict__ bias,
                                                 const float* __restrict__ resid,
                                                 float* __restrict__ C,
                                                 __nv_bfloat16* __restrict__ qbf,
                                                 __nv_bfloat16* __restrict__ kbf,
                                                 __nv_bfloat16* __restrict__ vbf,
                                                 int M, int N, int K) {
    extern __shared__ char smem[];
    const uint32_t sb = smem_u32(smem);

    const int tid  = threadIdx.x;
    const int wid  = tid >> 5;
    const int lane = tid & 31;
    const int gid  = lane >> 2;
    const int t4   = lane & 3;
    const int wm   = wid & 1;
    const int wn   = wid >> 1;
    const int lg   = lane >> 3;
    const int lr   = lane & 7;

    const int m0 = blockIdx.y * 128;
    const int n0 = blockIdx.x * 128;

    const int arow = (lg & 1) * 8 + lr;
    const int akof = (lg >> 1) * 16;
    const int brow = (lg >> 1) * 8 + lr;
    const int bkof = (lg & 1) * 16;

    float acc[4][4][4];
    #pragma unroll
    for (int i = 0; i < 4; i++)
        #pragma unroll
        for (int j = 0; j < 4; j++)
            #pragma unroll
            for (int q = 0; q < 4; q++) acc[i][j][q] = 0.f;

    const int NCH = K >> 6;              // 64-K chunks

    auto load_chunk = [&](int c, int buf) {
        const int kof = c * 64;
        const uint32_t abase = sb + buf * 2 * GTILE;
        const uint32_t bbase = abase + GTILE;
        #pragma unroll
        for (int it = 0; it < 4; it++) {
            const int idx = tid + it * 256;
            const int row = idx >> 3;
            const int c8  = (idx & 7) * 8;
            const uint32_t doff = (uint32_t)(row * GSTB + c8 * 2);
            CP_ASYNC16(abase + doff, A  + (size_t)(m0 + row) * K + kof + c8);
            CP_ASYNC16(bbase + doff, Bt + (size_t)(n0 + row) * K + kof + c8);
        }
        CP_COMMIT();
    };

    load_chunk(0, 0);

    for (int c = 0; c < NCH; c++) {
        const int buf = c & 1;
        if (c + 1 < NCH) { load_chunk(c + 1, buf ^ 1); CP_WAIT(1); }
        else             { CP_WAIT(0); }
        __syncthreads();

        const uint32_t abase = sb + buf * 2 * GTILE;
        const uint32_t bbase = abase + GTILE;

        #pragma unroll
        for (int ks = 0; ks < 4; ks++) {
            uint32_t af[4][4], bf[4][2];
            #pragma unroll
            for (int i = 0; i < 4; i++) {
                const uint32_t addr = abase +
                    (uint32_t)((wm * 64 + i * 16 + arow) * GSTB + akof + ks * 32);
                LDMX4(af[i][0], af[i][1], af[i][2], af[i][3], addr);
            }
            #pragma unroll
            for (int jp = 0; jp < 2; jp++) {
                const uint32_t addr = bbase +
                    (uint32_t)((wn * 32 + jp * 16 + brow) * GSTB + bkof + ks * 32);
                LDMX4(bf[2 * jp][0], bf[2 * jp][1], bf[2 * jp + 1][0], bf[2 * jp + 1][1], addr);
            }
            #pragma unroll
            for (int i = 0; i < 4; i++)
                #pragma unroll
                for (int j = 0; j < 4; j++)
                    mma_bf16(acc[i][j], af[i], bf[j]);
        }
        __syncthreads();
    }

    const bool q_out = (qbf != nullptr) && (n0 < HID);
    const bool k_out = (kbf != nullptr) && (n0 >= HID) && (n0 < 2 * HID);
    const bool v_out = (vbf != nullptr) && (n0 >= 2 * HID);
    const float qscale = 0.125f * LOG2E;

    #pragma unroll
    for (int i = 0; i < 4; i++) {
        const int r0 = m0 + wm * 64 + i * 16 + gid;
        #pragma unroll
        for (int j = 0; j < 4; j++) {
            const int col = n0 + wn * 32 + j * 8 + t4 * 2;
            const float2 bb = *(const float2*)(bias + col);
            float2 o0, o1;
            o0.x = acc[i][j][0] + bb.x;  o0.y = acc[i][j][1] + bb.y;
            o1.x = acc[i][j][2] + bb.x;  o1.y = acc[i][j][3] + bb.y;
            if (q_out || k_out || v_out) {
                __nv_bfloat16* dst = q_out ? qbf : (k_out ? kbf : vbf);
                const int d0 = col - (q_out ? 0 : (k_out ? HID : 2 * HID));
                if (q_out) {
                    o0.x *= qscale; o0.y *= qscale;
                    o1.x *= qscale; o1.y *= qscale;
                }
                __nv_bfloat162 v0, v1;
                v0.x = __float2bfloat16_rn(o0.x); v0.y = __float2bfloat16_rn(o0.y);
                v1.x = __float2bfloat16_rn(o1.x); v1.y = __float2bfloat16_rn(o1.y);
                *(__nv_bfloat162*)(dst + (size_t)r0 * HID + d0)       = v0;
                *(__nv_bfloat162*)(dst + (size_t)(r0 + 8) * HID + d0) = v1;
            } else {
                if (resid) {
                    const float2 ra = *(const float2*)(resid + (size_t)r0 * N + col);
                    const float2 rb = *(const float2*)(resid + (size_t)(r0 + 8) * N + col);
                    o0.x += ra.x; o0.y += ra.y;
                    o1.x += rb.x; o1.y += rb.y;
                }
                *(float2*)(C + (size_t)r0 * N + col)       = o0;
                *(float2*)(C + (size_t)(r0 + 8) * N + col) = o1;
            }
        }
    }
}

// ---------------------------------------------------------------------------
// Flash attention, all-bf16 MMA (m16n8k16), 64-key tiles, q-fastest grid.
// Mask (pre-scaled bf16) prefetched via cp.async alongside K/V.
// ---------------------------------------------------------------------------
static constexpr int KVSTB = 144;                    // K/V/mask smem row stride (bytes)
static constexpr int AKB   = 64 * KVSTB;             // 9216 B per K or V tile
static constexpr int AST   = 2 * AKB;                // K+V per stage: 18432 B
static constexpr int MKB   = 128 * KVSTB;            // 18432 B mask tile per stage
static constexpr int ASMEM = 2 * AST + 2 * MKB;      // 73728 B

__global__ void __launch_bounds__(256) attn_mma(const __nv_bfloat16* __restrict__ qbf,
                                                const __nv_bfloat16* __restrict__ kbf,
                                                const __nv_bfloat16* __restrict__ vbf,
                                                const __nv_bfloat16* __restrict__ mbf,
                                                __nv_bfloat16* __restrict__ out) {
    extern __shared__ char smem[];
    const uint32_t sb = smem_u32(smem);

    const int tid  = threadIdx.x;
    const int w    = tid >> 5;
    const int lane = tid & 31;
    const int gid  = lane >> 2;
    const int t4   = lane & 3;

    const int q0 = blockIdx.x * 128;
    const int h  = blockIdx.y;
    const int b  = blockIdx.z;

    const int lg = lane >> 3;
    const int lr = lane & 7;
    const int krow = ((lg >> 1) << 3) + lr;
    const int kkof = (lg & 1) * 16;
    const int vkof = (lg & 1) * 8;
    const int vdof = (lg >> 1) * 8;

    // ---- Q bf16 A-fragments: direct loads (pre-scaled in QKV epilogue) ----
    const int qr0 = b * SEQ + q0 + w * 16 + gid;
    const __nv_bfloat16* qb0 = qbf + (size_t)qr0 * HID + h * 64;
    const __nv_bfloat16* qb1 = qb0 + (size_t)8 * HID;
    uint32_t aq[4][4];
    #pragma unroll
    for (int ks = 0; ks < 4; ks++) {
        aq[ks][0] = *(const uint32_t*)(qb0 + ks * 16 + 2 * t4);
        aq[ks][1] = *(const uint32_t*)(qb1 + ks * 16 + 2 * t4);
        aq[ks][2] = *(const uint32_t*)(qb0 + ks * 16 + 8 + 2 * t4);
        aq[ks][3] = *(const uint32_t*)(qb1 + ks * 16 + 8 + 2 * t4);
    }

    float l0 = 0.f, l1 = 0.f;
    float acc[8][4];
    #pragma unroll
    for (int i = 0; i < 8; i++)
        #pragma unroll
        for (int q = 0; q < 4; q++) acc[i][q] = 0.f;

    const __nv_bfloat16* mbase = mbf + ((size_t)b * SEQ + q0) * SEQ;   // [128 rows][SEQ]

    auto load_kv = [&](int kt, int buf) {
        const int k0 = kt * 64;
        const __nv_bfloat16* srcK = kbf + ((size_t)(b * SEQ + k0)) * HID + h * 64;
        const __nv_bfloat16* srcV = vbf + ((size_t)(b * SEQ + k0)) * HID + h * 64;
        const uint32_t kb = sb + buf * AST;
        const uint32_t vb = kb + AKB;
        const uint32_t mb = sb + 2 * AST + buf * MKB;
        #pragma unroll
        for (int i = 0; i < 2; i++) {                 // K/V: 512 16B chunks each
            const int idx = tid + i * 256;
            const int row = idx >> 3;
            const int c8  = (idx & 7) * 8;
            CP_ASYNC16(kb + (uint32_t)(row * KVSTB + c8 * 2), srcK + (size_t)row * HID + c8);
            CP_ASYNC16(vb + (uint32_t)(row * KVSTB + c8 * 2), srcV + (size_t)row * HID + c8);
        }
        #pragma unroll
        for (int i = 0; i < 4; i++) {                 // mask: 1024 16B chunks (bf16)
            const int idx = tid + i * 256;
            const int row = idx >> 3;                 // 0..127 (q row)
            const int c8  = (idx & 7) * 8;            // bf16 col 0..56
            CP_ASYNC16(mb + (uint32_t)(row * KVSTB + c8 * 2),
                       mbase + (size_t)row * SEQ + k0 + c8);
        }
        CP_COMMIT();
    };

    constexpr int NIT = SEQ / 64;
    load_kv(0, 0);

    for (int kt = 0; kt < NIT; kt++) {
        const int buf = kt & 1;
        if (kt + 1 < NIT) { load_kv(kt + 1, buf ^ 1); CP_WAIT(1); }
        else              { CP_WAIT(0); }
        __syncthreads();

        const uint32_t kbase = sb + buf * AST;
        const uint32_t vbase = kbase + AKB;
        const __nv_bfloat16* Ms = (const __nv_bfloat16*)(smem + 2 * AST + buf * MKB);
        const __nv_bfloat16* ms0 = Ms + (w * 16 + gid) * 72 + 2 * t4;   // 72 bf16 = 144 B
        const __nv_bfloat16* ms1 = ms0 + 8 * 72;

        float sc[8][4];
        #pragma unroll
        for (int nt = 0; nt < 8; nt++)
            #pragma unroll
            for (int q = 0; q < 4; q++) sc[nt][q] = 0.f;

        #pragma unroll
        for (int ks = 0; ks < 4; ks++) {
            #pragma unroll
            for (int ntp = 0; ntp < 4; ntp++) {
                uint32_t r0, r1, r2, r3;
                const uint32_t addr = kbase +
                    (uint32_t)((ntp * 16 + krow) * KVSTB + kkof + ks * 32);
                LDMX4(r0, r1, r2, r3, addr);
                uint32_t b0[2] = {r0, r1}, b1[2] = {r2, r3};
                mma_bf16(sc[2 * ntp],     aq[ks], b0);
                mma_bf16(sc[2 * ntp + 1], aq[ks], b1);
            }
        }

        #pragma unroll
        for (int nt = 0; nt < 8; nt++) {
            const float2 mm0 = __bfloat1622float2(*(const __nv_bfloat162*)(ms0 + nt * 8));
            const float2 mm1 = __bfloat1622float2(*(const __nv_bfloat162*)(ms1 + nt * 8));
            sc[nt][0] = exp2f(sc[nt][0] + mm0.x);
            sc[nt][1] = exp2f(sc[nt][1] + mm0.y);
            sc[nt][2] = exp2f(sc[nt][2] + mm1.x);
            sc[nt][3] = exp2f(sc[nt][3] + mm1.y);
            l0 += sc[nt][0] + sc[nt][1];
            l1 += sc[nt][2] + sc[nt][3];
        }

        #pragma unroll
        for (int j = 0; j < 4; j++) {
            uint32_t pa[4];
            CVT_BF16X2(pa[0], sc[2 * j][1],     sc[2 * j][0]);
            CVT_BF16X2(pa[1], sc[2 * j][3],     sc[2 * j][2]);
            CVT_BF16X2(pa[2], sc[2 * j + 1][1], sc[2 * j + 1][0]);
            CVT_BF16X2(pa[3], sc[2 * j + 1][3], sc[2 * j + 1][2]);
            #pragma unroll
            for (int ndtp = 0; ndtp < 4; ndtp++) {
                uint32_t r0, r1, r2, r3;
                const uint32_t addr = vbase +
                    (uint32_t)((j * 16 + vkof + lr) * KVSTB + (ndtp * 16 + vdof) * 2);
                LDMX4T(r0, r1, r2, r3, addr);
                uint32_t v0[2] = {r0, r1}, v1[2] = {r2, r3};
                mma_bf16(acc[2 * ndtp],     pa, v0);
                mma_bf16(acc[2 * ndtp + 1], pa, v1);
            }
        }
        __syncthreads();
    }

    #pragma unroll
    for (int off = 1; off <= 2; off <<= 1) {
        l0 += __shfl_xor_sync(0xffffffffu, l0, off);
        l1 += __shfl_xor_sync(0xffffffffu, l1, off);
    }
    const float inv0 = 1.f / l0;
    const float inv1 = 1.f / l1;
    __nv_bfloat16* ob0 = out + (size_t)(b * SEQ + q0 + w * 16 + gid) * HID + h * 64;
    __nv_bfloat16* ob1 = ob0 + (size_t)8 * HID;
    #pragma unroll
    for (int ndt = 0; ndt < 8; ndt++) {
        __nv_bfloat162 v0, v1;
        v0.x = __float2bfloat16_rn(acc[ndt][0] * inv0);
        v0.y = __float2bfloat16_rn(acc[ndt][1] * inv0);
        v1.x = __float2bfloat16_rn(acc[ndt][2] * inv1);
        v1.y = __float2bfloat16_rn(acc[ndt][3] * inv1);
        *(__nv_bfloat162*)(ob0 + ndt * 8 + 2 * t4) = v0;
        *(__nv_bfloat162*)(ob1 + ndt * 8 + 2 * t4) = v1;
    }
}

// ---------------------------------------------------------------------------
// Launch
// ---------------------------------------------------------------------------
extern "C" void kernel_launch(void* const* d_in, const int* in_sizes, int n_in,
                              void* d_out, int out_size) {
    const float* hidden = (const float*)d_in[0];
    const float* mask   = (const float*)d_in[1];
    const float* w_qkv  = (const float*)d_in[2];
    const float* b_qkv  = (const float*)d_in[3];
    const float* w_out  = (const float*)d_in[4];
    const float* b_out  = (const float*)d_in[5];
    const float* ln_g   = (const float*)d_in[6];
    const float* ln_b   = (const float*)d_in[7];
    float* out = (float*)d_out;

    __nv_bfloat16 *xln = nullptr, *attnb = nullptr, *wqkvT = nullptr,
                  *woutT = nullptr, *qbfb = nullptr, *kbfb = nullptr,
                  *vbfb = nullptr, *mbfb = nullptr;
    cudaGetSymbolAddress((void**)&xln,   g_xln);
    cudaGetSymbolAddress((void**)&attnb, g_attn);
    cudaGetSymbolAddress((void**)&wqkvT, g_wqkvT);
    cudaGetSymbolAddress((void**)&woutT, g_woutT);
    cudaGetSymbolAddress((void**)&qbfb,  g_qbf);
    cudaGetSymbolAddress((void**)&kbfb,  g_kbf);
    cudaGetSymbolAddress((void**)&vbfb,  g_vbf);
    cudaGetSymbolAddress((void**)&mbfb,  g_mbf);

    cudaFuncSetAttribute(gemm_bf16, cudaFuncAttributeMaxDynamicSharedMemorySize, GSMEM);
    cudaFuncSetAttribute(attn_mma, cudaFuncAttributeMaxDynamicSharedMemorySize, ASMEM);

    ln_kernel<<<ROWS, 256>>>(hidden, ln_g, ln_b, xln);
    mask_bf<<<(BATCH * SEQ * SEQ) / 1024, 256>>>(mask, mbfb);
    transpose_bf<<<dim3(3 * HID / 32, HID / 32), dim3(32, 8)>>>(w_qkv, wqkvT, HID, 3 * HID);
    transpose_bf<<<dim3(HID / 32, HID / 32), dim3(32, 8)>>>(w_out, woutT, HID, HID);

    gemm_bf16<<<dim3(3 * HID / 128, ROWS / 128), 256, GSMEM>>>(
        xln, wqkvT, b_qkv, nullptr, nullptr, qbfb, kbfb, vbfb, ROWS, 3 * HID, HID);

    attn_mma<<<dim3(SEQ / 128, HEADS, BATCH), 256, ASMEM>>>(qbfb, kbfb, vbfb, mbfb, attnb);

    gemm_bf16<<<dim3(HID / 128, ROWS / 128), 256, GSMEM>>>(
        attnb, woutT, b_out, hidden, out, nullptr, nullptr, nullptr, ROWS, HID, HID);
}